// round 1
// baseline (speedup 1.0000x reference)
#include <cuda_runtime.h>
#include <math.h>

#define Bsz   2
#define Sq    2048
#define Dm    1024
#define Hh    16
#define DKd   64
#define Mtot  4096
#define NQb   8
#define DIMq  256
#define EPSf  1e-5f
#define ATT_PAD 68

// ---------------- scratch (device globals; no allocs allowed) ----------------
__device__ float g_q[Mtot * Dm];
__device__ float g_k[Mtot * Dm];
__device__ float g_v[Mtot * Dm];
__device__ float g_o[Mtot * Dm];
__device__ float g_proj[Mtot * Dm];
__device__ float g_x1[Mtot * Dm];

// ---------------- SGEMM: C[M,N] = A[M,K] * W[N,K]^T ----------------
// 128x128 tile, K-step 8, 256 threads, 8x8 per-thread microtile.
__global__ __launch_bounds__(256) void sgemm_nt(const float* __restrict__ A,
                                                const float* __restrict__ W,
                                                float* __restrict__ C,
                                                int M, int N, int K)
{
    __shared__ float As[8][128];
    __shared__ float Ws[8][128];
    const int tid = threadIdx.x;
    const int tx = tid & 15;   // n dir
    const int ty = tid >> 4;   // m dir
    const int row0 = blockIdx.y << 7;
    const int col0 = blockIdx.x << 7;
    const int lrow = tid >> 1;           // 0..127
    const int lcol = (tid & 1) << 2;     // 0 or 4

    const float* Aptr = A + (size_t)(row0 + lrow) * K + lcol;
    const float* Wptr = W + (size_t)(col0 + lrow) * K + lcol;

    float acc[8][8];
#pragma unroll
    for (int i = 0; i < 8; i++)
#pragma unroll
        for (int j = 0; j < 8; j++) acc[i][j] = 0.f;

    for (int kt = 0; kt < K; kt += 8) {
        float4 av = *reinterpret_cast<const float4*>(Aptr + kt);
        float4 wv = *reinterpret_cast<const float4*>(Wptr + kt);
        As[lcol + 0][lrow] = av.x; As[lcol + 1][lrow] = av.y;
        As[lcol + 2][lrow] = av.z; As[lcol + 3][lrow] = av.w;
        Ws[lcol + 0][lrow] = wv.x; Ws[lcol + 1][lrow] = wv.y;
        Ws[lcol + 2][lrow] = wv.z; Ws[lcol + 3][lrow] = wv.w;
        __syncthreads();
#pragma unroll
        for (int kk = 0; kk < 8; kk++) {
            float ar[8], wr[8];
#pragma unroll
            for (int i = 0; i < 8; i++) ar[i] = As[kk][(ty << 3) + i];
#pragma unroll
            for (int j = 0; j < 8; j++) wr[j] = Ws[kk][(tx << 3) + j];
#pragma unroll
            for (int i = 0; i < 8; i++)
#pragma unroll
                for (int j = 0; j < 8; j++)
                    acc[i][j] = fmaf(ar[i], wr[j], acc[i][j]);
        }
        __syncthreads();
    }
#pragma unroll
    for (int i = 0; i < 8; i++) {
        float* crow = C + (size_t)(row0 + (ty << 3) + i) * N + col0 + (tx << 3);
        *reinterpret_cast<float4*>(crow)     = make_float4(acc[i][0], acc[i][1], acc[i][2], acc[i][3]);
        *reinterpret_cast<float4*>(crow + 4) = make_float4(acc[i][4], acc[i][5], acc[i][6], acc[i][7]);
    }
}

// ---------------- Flash attention (fp32), 64x64 tiles ----------------
// q,k,v,o layout: [B, S, H, 64] (contiguous head dim)
__global__ __launch_bounds__(256) void flash_attn(const float* __restrict__ q,
                                                  const float* __restrict__ k,
                                                  const float* __restrict__ v,
                                                  float* __restrict__ o)
{
    extern __shared__ float sm[];
    float* Qs = sm;                        // 64 x ATT_PAD
    float* Ks = Qs + 64 * ATT_PAD;
    float* Vs = Ks + 64 * ATT_PAD;
    float* Ps = Vs + 64 * ATT_PAD;

    const int tid = threadIdx.x;
    const int tx = tid & 15, ty = tid >> 4;
    const int r0 = ty << 2, c0 = tx << 2;
    const int h = blockIdx.y, b = blockIdx.z;
    const int q0 = blockIdx.x << 6;

    // load Q tile (scaled by 1/sqrt(dk) = 0.125)
#pragma unroll
    for (int j = 0; j < 4; j++) {
        int idx = tid + (j << 8);          // float4 id, 0..1023
        int row = idx >> 4;
        int c4  = (idx & 15) << 2;
        float4 qv = *reinterpret_cast<const float4*>(
            q + (((size_t)(b * Sq + q0 + row) * Hh + h) << 6) + c4);
        float* dst = Qs + row * ATT_PAD + c4;
        dst[0] = qv.x * 0.125f; dst[1] = qv.y * 0.125f;
        dst[2] = qv.z * 0.125f; dst[3] = qv.w * 0.125f;
    }

    float m_run[4], l_run[4], oacc[4][4];
#pragma unroll
    for (int i = 0; i < 4; i++) {
        m_run[i] = -1e30f; l_run[i] = 0.f;
#pragma unroll
        for (int j = 0; j < 4; j++) oacc[i][j] = 0.f;
    }

    for (int kt = 0; kt < Sq; kt += 64) {
        __syncthreads();
        // load K, V tiles
#pragma unroll
        for (int j = 0; j < 4; j++) {
            int idx = tid + (j << 8);
            int row = idx >> 4;
            int c4  = (idx & 15) << 2;
            size_t gofs = (((size_t)(b * Sq + kt + row) * Hh + h) << 6) + c4;
            float4 kv = *reinterpret_cast<const float4*>(k + gofs);
            float4 vv = *reinterpret_cast<const float4*>(v + gofs);
            *reinterpret_cast<float4*>(Ks + row * ATT_PAD + c4) = kv;
            *reinterpret_cast<float4*>(Vs + row * ATT_PAD + c4) = vv;
        }
        __syncthreads();

        // S = Q K^T (4x4 per thread)
        float s[4][4];
#pragma unroll
        for (int i = 0; i < 4; i++)
#pragma unroll
            for (int j = 0; j < 4; j++) s[i][j] = 0.f;
#pragma unroll 16
        for (int kk = 0; kk < 64; kk++) {
            float qa[4], kb[4];
#pragma unroll
            for (int i = 0; i < 4; i++) qa[i] = Qs[(r0 + i) * ATT_PAD + kk];
#pragma unroll
            for (int j = 0; j < 4; j++) kb[j] = Ks[(c0 + j) * ATT_PAD + kk];
#pragma unroll
            for (int i = 0; i < 4; i++)
#pragma unroll
                for (int j = 0; j < 4; j++)
                    s[i][j] = fmaf(qa[i], kb[j], s[i][j]);
        }

        // online softmax; rows live across the 16 tx threads (width-16 shuffles)
#pragma unroll
        for (int i = 0; i < 4; i++) {
            float mx = fmaxf(fmaxf(s[i][0], s[i][1]), fmaxf(s[i][2], s[i][3]));
#pragma unroll
            for (int off = 1; off < 16; off <<= 1)
                mx = fmaxf(mx, __shfl_xor_sync(0xffffffffu, mx, off, 16));
            float mnew  = fmaxf(m_run[i], mx);
            float alpha = __expf(m_run[i] - mnew);
            float ps = 0.f;
#pragma unroll
            for (int jj = 0; jj < 4; jj++) {
                float p = __expf(s[i][jj] - mnew);
                Ps[(r0 + i) * ATT_PAD + c0 + jj] = p;
                ps += p;
            }
#pragma unroll
            for (int off = 1; off < 16; off <<= 1)
                ps += __shfl_xor_sync(0xffffffffu, ps, off, 16);
            l_run[i] = l_run[i] * alpha + ps;
            m_run[i] = mnew;
#pragma unroll
            for (int jj = 0; jj < 4; jj++) oacc[i][jj] *= alpha;
        }
        __syncthreads();

        // O += P V
#pragma unroll 16
        for (int kk = 0; kk < 64; kk++) {
            float pa[4], vb[4];
#pragma unroll
            for (int i = 0; i < 4; i++) pa[i] = Ps[(r0 + i) * ATT_PAD + kk];
#pragma unroll
            for (int j = 0; j < 4; j++) vb[j] = Vs[kk * ATT_PAD + c0 + j];
#pragma unroll
            for (int i = 0; i < 4; i++)
#pragma unroll
                for (int j = 0; j < 4; j++)
                    oacc[i][j] = fmaf(pa[i], vb[j], oacc[i][j]);
        }
    }

#pragma unroll
    for (int i = 0; i < 4; i++) {
        float inv = 1.f / l_run[i];
        float4 ov = make_float4(oacc[i][0] * inv, oacc[i][1] * inv,
                                oacc[i][2] * inv, oacc[i][3] * inv);
        *reinterpret_cast<float4*>(
            o + (((size_t)(b * Sq + q0 + r0 + i) * Hh + h) << 6) + c0) = ov;
    }
}

// ---------------- residual + LayerNorm (block per row) ----------------
__global__ __launch_bounds__(256) void add_ln(const float* __restrict__ xa,
                                              const float* __restrict__ xb,
                                              const float* __restrict__ g,
                                              const float* __restrict__ bb,
                                              float* __restrict__ out)
{
    __shared__ float red[16];
    const int row = blockIdx.x, tid = threadIdx.x;
    const int lane = tid & 31, wid = tid >> 5;
    const float* pa = xa + (size_t)row * Dm;
    const float* pb = xb + (size_t)row * Dm;

    float y[4], sum = 0.f, sq = 0.f;
#pragma unroll
    for (int j = 0; j < 4; j++) {
        int d = tid + (j << 8);
        float yv = pa[d] + pb[d];
        y[j] = yv; sum += yv; sq = fmaf(yv, yv, sq);
    }
#pragma unroll
    for (int off = 16; off; off >>= 1) {
        sum += __shfl_xor_sync(0xffffffffu, sum, off);
        sq  += __shfl_xor_sync(0xffffffffu, sq, off);
    }
    if (lane == 0) { red[wid] = sum; red[8 + wid] = sq; }
    __syncthreads();
    float tsum = 0.f, tsq = 0.f;
#pragma unroll
    for (int w = 0; w < 8; w++) { tsum += red[w]; tsq += red[8 + w]; }
    float mean = tsum * (1.f / 1024.f);
    float var  = tsq * (1.f / 1024.f) - mean * mean;
    float rstd = rsqrtf(var + EPSf);
#pragma unroll
    for (int j = 0; j < 4; j++) {
        int d = tid + (j << 8);
        out[(size_t)row * Dm + d] = (y[j] - mean) * rstd * g[d] + bb[d];
    }
}

// ---------------- quantum FFN + residual + LN, fully fused (block per token) --
// 256 threads == 256 statevector amplitudes.
__global__ __launch_bounds__(256) void quantum_tail(const float* __restrict__ x1,
                                                    const float* __restrict__ Win,
                                                    const float* __restrict__ b_in,
                                                    const float* __restrict__ Wout,
                                                    const float* __restrict__ b_out,
                                                    const float* __restrict__ ry,
                                                    const float* __restrict__ g2,
                                                    const float* __restrict__ b2,
                                                    float* __restrict__ out)
{
    const int row = blockIdx.x;
    const int tid = threadIdx.x;
    const int lane = tid & 31, wid = tid >> 5;
    const float* xr = x1 + (size_t)row * Dm;

    __shared__ float redw[64];       // 8 warps x 8 partials
    __shared__ float angs[8];
    __shared__ float ezs[8];
    __shared__ float2 st[2][DIMq];

    // ---- angles: ang[q] = 0.5 * (x1 . Win[q] + b_in[q]) ----
    float xv[4];
    float accq[8] = {0, 0, 0, 0, 0, 0, 0, 0};
#pragma unroll
    for (int j = 0; j < 4; j++) {
        int d = tid + (j << 8);
        float xval = xr[d];
        xv[j] = xval;
#pragma unroll
        for (int qq = 0; qq < 8; qq++)
            accq[qq] = fmaf(xval, Win[qq * Dm + d], accq[qq]);
    }
#pragma unroll
    for (int qq = 0; qq < 8; qq++) {
        float vsum = accq[qq];
#pragma unroll
        for (int off = 16; off; off >>= 1)
            vsum += __shfl_xor_sync(0xffffffffu, vsum, off);
        if (lane == 0) redw[wid * 8 + qq] = vsum;
    }
    __syncthreads();
    if (tid < 8) {
        float s = b_in[tid];
#pragma unroll
        for (int w = 0; w < 8; w++) s += redw[w * 8 + tid];
        angs[tid] = s * 0.5f;
    }
    // ---- init statevector |0...0> ----
    st[0][tid] = make_float2(tid == 0 ? 1.f : 0.f, 0.f);
    __syncthreads();

    int curb = 0;
    // RX(ang[w]) on each wire (MSB order: mask = 1 << (7-w))
#pragma unroll
    for (int w = 0; w < 8; w++) {
        int mask = 1 << (7 - w);
        float sn, cs;
        __sincosf(angs[w], &sn, &cs);
        float2 a  = st[curb][tid];
        float2 bb = st[curb][tid ^ mask];
        st[curb ^ 1][tid] = make_float2(fmaf(cs, a.x,  sn * bb.y),
                                        fmaf(cs, a.y, -sn * bb.x));
        curb ^= 1;
        __syncthreads();
    }
    // RY(ry[w]) shared angles
#pragma unroll
    for (int w = 0; w < 8; w++) {
        int mask = 1 << (7 - w);
        float sn, cs;
        __sincosf(ry[w] * 0.5f, &sn, &cs);
        float2 a  = st[curb][tid];
        float2 bb = st[curb][tid ^ mask];
        float sg = (tid & mask) ? sn : -sn;
        st[curb ^ 1][tid] = make_float2(fmaf(cs, a.x, sg * bb.x),
                                        fmaf(cs, a.y, sg * bb.y));
        curb ^= 1;
        __syncthreads();
    }
    // CNOT chain (controls 0..6, target = control+1) collapsed into one permutation
    int src = tid;
#pragma unroll
    for (int c = 6; c >= 0; c--) {
        int cmask = 1 << (7 - c);
        int tmask = cmask >> 1;
        if (src & cmask) src ^= tmask;
    }
    float2 fa = st[curb][src];
    float p = fa.x * fa.x + fa.y * fa.y;

    // ---- expZ[w] = sum_i (+/-) p_i ----
#pragma unroll
    for (int w = 0; w < 8; w++) {
        float vsum = ((tid >> (7 - w)) & 1) ? -p : p;
#pragma unroll
        for (int off = 16; off; off >>= 1)
            vsum += __shfl_xor_sync(0xffffffffu, vsum, off);
        if (lane == 0) redw[wid * 8 + w] = vsum;
    }
    __syncthreads();
    if (tid < 8) {
        float s = 0.f;
#pragma unroll
        for (int w = 0; w < 8; w++) s += redw[w * 8 + tid];
        ezs[tid] = s;
    }
    __syncthreads();
    float e[8];
#pragma unroll
    for (int qq = 0; qq < 8; qq++) e[qq] = ezs[qq];

    // ---- ffn out = relu(expz @ Wout^T + b_out); y = x1 + ffn; LN(y) ----
    float y[4], sum = 0.f, sq = 0.f;
#pragma unroll
    for (int j = 0; j < 4; j++) {
        int d = tid + (j << 8);
        const float4* wrow = reinterpret_cast<const float4*>(Wout + (size_t)d * 8);
        float4 w0 = wrow[0], w1 = wrow[1];
        float acc = b_out[d];
        acc = fmaf(e[0], w0.x, acc); acc = fmaf(e[1], w0.y, acc);
        acc = fmaf(e[2], w0.z, acc); acc = fmaf(e[3], w0.w, acc);
        acc = fmaf(e[4], w1.x, acc); acc = fmaf(e[5], w1.y, acc);
        acc = fmaf(e[6], w1.z, acc); acc = fmaf(e[7], w1.w, acc);
        acc = fmaxf(acc, 0.f);
        float yv = xv[j] + acc;
        y[j] = yv; sum += yv; sq = fmaf(yv, yv, sq);
    }
    __syncthreads();   // redw reuse guard
#pragma unroll
    for (int off = 16; off; off >>= 1) {
        sum += __shfl_xor_sync(0xffffffffu, sum, off);
        sq  += __shfl_xor_sync(0xffffffffu, sq, off);
    }
    if (lane == 0) { redw[wid] = sum; redw[8 + wid] = sq; }
    __syncthreads();
    float tsum = 0.f, tsq = 0.f;
#pragma unroll
    for (int w = 0; w < 8; w++) { tsum += redw[w]; tsq += redw[8 + w]; }
    float mean = tsum * (1.f / 1024.f);
    float var  = tsq * (1.f / 1024.f) - mean * mean;
    float rstd = rsqrtf(var + EPSf);
#pragma unroll
    for (int j = 0; j < 4; j++) {
        int d = tid + (j << 8);
        out[(size_t)row * Dm + d] = (y[j] - mean) * rstd * g2[d] + b2[d];
    }
}

// ---------------- launch ----------------
extern "C" void kernel_launch(void* const* d_in, const int* in_sizes, int n_in,
                              void* d_out, int out_size)
{
    const float* x     = (const float*)d_in[0];
    const float* Wq    = (const float*)d_in[1];
    const float* Wk    = (const float*)d_in[2];
    const float* Wv    = (const float*)d_in[3];
    const float* Wo    = (const float*)d_in[4];
    const float* g1    = (const float*)d_in[5];
    const float* b1    = (const float*)d_in[6];
    const float* g2    = (const float*)d_in[7];
    const float* b2    = (const float*)d_in[8];
    const float* Win   = (const float*)d_in[9];
    const float* b_in  = (const float*)d_in[10];
    const float* Wout  = (const float*)d_in[11];
    const float* b_out = (const float*)d_in[12];
    const float* ry    = (const float*)d_in[13];
    float* out = (float*)d_out;

    float *q, *k, *v, *o, *proj, *x1;
    cudaGetSymbolAddress((void**)&q,    g_q);
    cudaGetSymbolAddress((void**)&k,    g_k);
    cudaGetSymbolAddress((void**)&v,    g_v);
    cudaGetSymbolAddress((void**)&o,    g_o);
    cudaGetSymbolAddress((void**)&proj, g_proj);
    cudaGetSymbolAddress((void**)&x1,   g_x1);

    const int attn_smem = 4 * 64 * ATT_PAD * (int)sizeof(float);  // 69632 B
    cudaFuncSetAttribute(flash_attn, cudaFuncAttributeMaxDynamicSharedMemorySize,
                         attn_smem);

    dim3 ggrid(Dm / 128, Mtot / 128);
    sgemm_nt<<<ggrid, 256>>>(x, Wq, q, Mtot, Dm, Dm);
    sgemm_nt<<<ggrid, 256>>>(x, Wk, k, Mtot, Dm, Dm);
    sgemm_nt<<<ggrid, 256>>>(x, Wv, v, Mtot, Dm, Dm);
    flash_attn<<<dim3(Sq / 64, Hh, Bsz), 256, attn_smem>>>(q, k, v, o);
    sgemm_nt<<<ggrid, 256>>>(o, Wo, proj, Mtot, Dm, Dm);
    add_ln<<<Mtot, 256>>>(x, proj, g1, b1, x1);
    quantum_tail<<<Mtot, 256>>>(x1, Win, b_in, Wout, b_out, ry, g2, b2, out);
}

// round 3
// speedup vs baseline: 1.4008x; 1.4008x over previous
#include <cuda_runtime.h>
#include <math.h>
#include <cstdint>

#define Bsz   2
#define Sq    2048
#define Dm    1024
#define Hh    16
#define Mtot  4096
#define DIMq  256
#define EPSf  1e-5f
#define ATT_PAD 68

// ---------------- scratch (device globals; no allocs allowed) ----------------
__device__ float g_q[Mtot * Dm];
__device__ float g_k[Mtot * Dm];
__device__ float g_v[Mtot * Dm];
__device__ float g_o[Mtot * Dm];
__device__ float g_proj[Mtot * Dm];
__device__ float g_x1[Mtot * Dm];

// ======================= helpers =======================
__device__ __forceinline__ uint32_t smem_to_u32(const void* p) {
    uint32_t a;
    asm("{ .reg .u64 t; cvta.to.shared.u64 t, %1; cvt.u32.u64 %0, t; }" : "=r"(a) : "l"(p));
    return a;
}
__device__ __forceinline__ void cp16(uint32_t sm, const void* g) {
    asm volatile("cp.async.cg.shared.global [%0], [%1], 16;" :: "r"(sm), "l"(g));
}
__device__ __forceinline__ void cp_commit() {
    asm volatile("cp.async.commit_group;");
}
template <int N>
__device__ __forceinline__ void cp_wait() {
    asm volatile("cp.async.wait_group %0;" :: "n"(N));
}
__device__ __forceinline__ uint32_t f2tf32(float x) {
    uint32_t r;
    asm("cvt.rna.tf32.f32 %0, %1;" : "=r"(r) : "f"(x));
    return r;
}
__device__ __forceinline__ void mma_tf32(float c[4], const uint32_t a[4], const uint32_t b[2]) {
    asm volatile(
        "mma.sync.aligned.m16n8k8.row.col.f32.tf32.tf32.f32 "
        "{%0,%1,%2,%3}, {%4,%5,%6,%7}, {%8,%9}, {%0,%1,%2,%3};"
        : "+f"(c[0]), "+f"(c[1]), "+f"(c[2]), "+f"(c[3])
        : "r"(a[0]), "r"(a[1]), "r"(a[2]), "r"(a[3]), "r"(b[0]), "r"(b[1]));
}

// ============ tf32 mma.sync GEMM: C[M,1024] = A[M,1024] * W[1024,1024]^T =====
// Block 128(M) x 256(N), K-stage 32, 3-stage cp.async pipeline, 8 warps (64x64).
#define BM 128
#define BN 256
#define BK 32
#define LDP 36                       // smem row stride (floats): 32 + 4 pad
#define A_STAGE_B (BM * LDP * 4)     // 18432 B
#define B_STAGE_B (BN * LDP * 4)     // 36864 B
#define GSMEM (3 * (A_STAGE_B + B_STAGE_B))  // 165888 B
#define NKT (Dm / BK)                // 32

__global__ __launch_bounds__(256, 1) void gemm_mma(const float* __restrict__ A,
                                                   const float* __restrict__ W,
                                                   float* __restrict__ C)
{
    extern __shared__ __align__(16) char gsm[];
    const uint32_t usm = smem_to_u32(gsm);
    const uint32_t usmA = usm;
    const uint32_t usmB = usm + 3 * A_STAGE_B;

    const int tid  = threadIdx.x;
    const int wid  = tid >> 5;
    const int lane = tid & 31;
    const int grp  = lane >> 2;      // 0..7
    const int tig  = lane & 3;       // 0..3
    const int wm   = wid >> 2;       // 0..1 -> m offset 64*wm
    const int wn   = wid & 3;        // 0..3 -> n offset 64*wn

    const int aRow0 = blockIdx.y * BM;
    const int bRow0 = blockIdx.x * BN;

    // per-thread load offsets (constant across stages)
    int aSm[4], bSm[8];
    int aGm[4], bGm[8];
#pragma unroll
    for (int i = 0; i < 4; i++) {
        int e = tid + (i << 8);
        int r = e >> 3, c4 = (e & 7) << 2;
        aSm[i] = (r * LDP + c4) * 4;
        aGm[i] = r * Dm + c4;
    }
#pragma unroll
    for (int i = 0; i < 8; i++) {
        int e = tid + (i << 8);
        int r = e >> 3, c4 = (e & 7) << 2;
        bSm[i] = (r * LDP + c4) * 4;
        bGm[i] = r * Dm + c4;
    }
    const float* gA = A + (size_t)aRow0 * Dm;
    const float* gB = W + (size_t)bRow0 * Dm;

    float acc[4][8][4];
#pragma unroll
    for (int im = 0; im < 4; im++)
#pragma unroll
        for (int jn = 0; jn < 8; jn++)
#pragma unroll
            for (int t = 0; t < 4; t++) acc[im][jn][t] = 0.f;

    // prologue: stages 0, 1
#pragma unroll
    for (int p = 0; p < 2; p++) {
        uint32_t sa = usmA + p * A_STAGE_B;
        uint32_t sb = usmB + p * B_STAGE_B;
        const float* ka = gA + p * BK;
        const float* kb = gB + p * BK;
#pragma unroll
        for (int i = 0; i < 4; i++) cp16(sa + aSm[i], ka + aGm[i]);
#pragma unroll
        for (int i = 0; i < 8; i++) cp16(sb + bSm[i], kb + bGm[i]);
        cp_commit();
    }

    for (int kt = 0; kt < NKT; kt++) {
        cp_wait<1>();
        __syncthreads();

        // issue stage kt+2 (into buffer (kt+2)%3, consumed at kt-1, safe after sync)
        if (kt + 2 < NKT) {
            int s = (kt + 2) % 3;
            uint32_t sa = usmA + s * A_STAGE_B;
            uint32_t sb = usmB + s * B_STAGE_B;
            const float* ka = gA + (kt + 2) * BK;
            const float* kb = gB + (kt + 2) * BK;
#pragma unroll
            for (int i = 0; i < 4; i++) cp16(sa + aSm[i], ka + aGm[i]);
#pragma unroll
            for (int i = 0; i < 8; i++) cp16(sb + bSm[i], kb + bGm[i]);
        }
        cp_commit();   // always commit to keep group accounting uniform

        const float* As = (const float*)(gsm + (kt % 3) * A_STAGE_B);
        const float* Bs = (const float*)(gsm + 3 * A_STAGE_B + (kt % 3) * B_STAGE_B);

#pragma unroll
        for (int k8 = 0; k8 < 4; k8++) {
            const int kb = k8 * 8 + tig;
            uint32_t afr[4][4], bfr[8][2];
#pragma unroll
            for (int im = 0; im < 4; im++) {
                int row = wm * 64 + im * 16 + grp;
                afr[im][0] = f2tf32(As[row * LDP + kb]);
                afr[im][1] = f2tf32(As[(row + 8) * LDP + kb]);
                afr[im][2] = f2tf32(As[row * LDP + kb + 4]);
                afr[im][3] = f2tf32(As[(row + 8) * LDP + kb + 4]);
            }
#pragma unroll
            for (int jn = 0; jn < 8; jn++) {
                int brow = wn * 64 + jn * 8 + grp;
                bfr[jn][0] = f2tf32(Bs[brow * LDP + kb]);
                bfr[jn][1] = f2tf32(Bs[brow * LDP + kb + 4]);
            }
#pragma unroll
            for (int im = 0; im < 4; im++)
#pragma unroll
                for (int jn = 0; jn < 8; jn++)
                    mma_tf32(acc[im][jn], afr[im], bfr[jn]);
        }
        __syncthreads();
    }

    // epilogue
    const int rowBase = aRow0 + wm * 64;
    const int colBase = bRow0 + wn * 64;
#pragma unroll
    for (int im = 0; im < 4; im++) {
        int r0 = rowBase + im * 16 + grp;
#pragma unroll
        for (int jn = 0; jn < 8; jn++) {
            int col = colBase + jn * 8 + 2 * tig;
            float2 v01 = make_float2(acc[im][jn][0], acc[im][jn][1]);
            float2 v23 = make_float2(acc[im][jn][2], acc[im][jn][3]);
            *reinterpret_cast<float2*>(C + (size_t)r0 * Dm + col) = v01;
            *reinterpret_cast<float2*>(C + (size_t)(r0 + 8) * Dm + col) = v23;
        }
    }
}

// ---------------- Flash attention (fp32), 64x64 tiles ----------------
__global__ __launch_bounds__(256) void flash_attn(const float* __restrict__ q,
                                                  const float* __restrict__ k,
                                                  const float* __restrict__ v,
                                                  float* __restrict__ o)
{
    extern __shared__ float sm[];
    float* Qs = sm;
    float* Ks = Qs + 64 * ATT_PAD;
    float* Vs = Ks + 64 * ATT_PAD;
    float* Ps = Vs + 64 * ATT_PAD;

    const int tid = threadIdx.x;
    const int tx = tid & 15, ty = tid >> 4;
    const int r0 = ty << 2, c0 = tx << 2;
    const int h = blockIdx.y, b = blockIdx.z;
    const int q0 = blockIdx.x << 6;

#pragma unroll
    for (int j = 0; j < 4; j++) {
        int idx = tid + (j << 8);
        int row = idx >> 4;
        int c4  = (idx & 15) << 2;
        float4 qv = *reinterpret_cast<const float4*>(
            q + (((size_t)(b * Sq + q0 + row) * Hh + h) << 6) + c4);
        float* dst = Qs + row * ATT_PAD + c4;
        dst[0] = qv.x * 0.125f; dst[1] = qv.y * 0.125f;
        dst[2] = qv.z * 0.125f; dst[3] = qv.w * 0.125f;
    }

    float m_run[4], l_run[4], oacc[4][4];
#pragma unroll
    for (int i = 0; i < 4; i++) {
        m_run[i] = -1e30f; l_run[i] = 0.f;
#pragma unroll
        for (int j = 0; j < 4; j++) oacc[i][j] = 0.f;
    }

    for (int kt = 0; kt < Sq; kt += 64) {
        __syncthreads();
#pragma unroll
        for (int j = 0; j < 4; j++) {
            int idx = tid + (j << 8);
            int row = idx >> 4;
            int c4  = (idx & 15) << 2;
            size_t gofs = (((size_t)(b * Sq + kt + row) * Hh + h) << 6) + c4;
            float4 kv = *reinterpret_cast<const float4*>(k + gofs);
            float4 vv = *reinterpret_cast<const float4*>(v + gofs);
            *reinterpret_cast<float4*>(Ks + row * ATT_PAD + c4) = kv;
            *reinterpret_cast<float4*>(Vs + row * ATT_PAD + c4) = vv;
        }
        __syncthreads();

        float s[4][4];
#pragma unroll
        for (int i = 0; i < 4; i++)
#pragma unroll
            for (int j = 0; j < 4; j++) s[i][j] = 0.f;
#pragma unroll 16
        for (int kk = 0; kk < 64; kk++) {
            float qa[4], kb[4];
#pragma unroll
            for (int i = 0; i < 4; i++) qa[i] = Qs[(r0 + i) * ATT_PAD + kk];
#pragma unroll
            for (int j = 0; j < 4; j++) kb[j] = Ks[(c0 + j) * ATT_PAD + kk];
#pragma unroll
            for (int i = 0; i < 4; i++)
#pragma unroll
                for (int j = 0; j < 4; j++)
                    s[i][j] = fmaf(qa[i], kb[j], s[i][j]);
        }

#pragma unroll
        for (int i = 0; i < 4; i++) {
            float mx = fmaxf(fmaxf(s[i][0], s[i][1]), fmaxf(s[i][2], s[i][3]));
#pragma unroll
            for (int off = 1; off < 16; off <<= 1)
                mx = fmaxf(mx, __shfl_xor_sync(0xffffffffu, mx, off, 16));
            float mnew  = fmaxf(m_run[i], mx);
            float alpha = __expf(m_run[i] - mnew);
            float ps = 0.f;
#pragma unroll
            for (int jj = 0; jj < 4; jj++) {
                float p = __expf(s[i][jj] - mnew);
                Ps[(r0 + i) * ATT_PAD + c0 + jj] = p;
                ps += p;
            }
#pragma unroll
            for (int off = 1; off < 16; off <<= 1)
                ps += __shfl_xor_sync(0xffffffffu, ps, off, 16);
            l_run[i] = l_run[i] * alpha + ps;
            m_run[i] = mnew;
#pragma unroll
            for (int jj = 0; jj < 4; jj++) oacc[i][jj] *= alpha;
        }
        __syncthreads();

#pragma unroll 16
        for (int kk = 0; kk < 64; kk++) {
            float pa[4], vb[4];
#pragma unroll
            for (int i = 0; i < 4; i++) pa[i] = Ps[(r0 + i) * ATT_PAD + kk];
#pragma unroll
            for (int j = 0; j < 4; j++) vb[j] = Vs[kk * ATT_PAD + c0 + j];
#pragma unroll
            for (int i = 0; i < 4; i++)
#pragma unroll
                for (int j = 0; j < 4; j++)
                    oacc[i][j] = fmaf(pa[i], vb[j], oacc[i][j]);
        }
    }

#pragma unroll
    for (int i = 0; i < 4; i++) {
        float inv = 1.f / l_run[i];
        float4 ov = make_float4(oacc[i][0] * inv, oacc[i][1] * inv,
                                oacc[i][2] * inv, oacc[i][3] * inv);
        *reinterpret_cast<float4*>(
            o + (((size_t)(b * Sq + q0 + r0 + i) * Hh + h) << 6) + c0) = ov;
    }
}

// ---------------- residual + LayerNorm ----------------
__global__ __launch_bounds__(256) void add_ln(const float* __restrict__ xa,
                                              const float* __restrict__ xb,
                                              const float* __restrict__ g,
                                              const float* __restrict__ bb,
                                              float* __restrict__ out)
{
    __shared__ float red[16];
    const int row = blockIdx.x, tid = threadIdx.x;
    const int lane = tid & 31, wid = tid >> 5;
    const float* pa = xa + (size_t)row * Dm;
    const float* pb = xb + (size_t)row * Dm;

    float y[4], sum = 0.f, sq = 0.f;
#pragma unroll
    for (int j = 0; j < 4; j++) {
        int d = tid + (j << 8);
        float yv = pa[d] + pb[d];
        y[j] = yv; sum += yv; sq = fmaf(yv, yv, sq);
    }
#pragma unroll
    for (int off = 16; off; off >>= 1) {
        sum += __shfl_xor_sync(0xffffffffu, sum, off);
        sq  += __shfl_xor_sync(0xffffffffu, sq, off);
    }
    if (lane == 0) { red[wid] = sum; red[8 + wid] = sq; }
    __syncthreads();
    float tsum = 0.f, tsq = 0.f;
#pragma unroll
    for (int w = 0; w < 8; w++) { tsum += red[w]; tsq += red[8 + w]; }
    float mean = tsum * (1.f / 1024.f);
    float var  = tsq * (1.f / 1024.f) - mean * mean;
    float rstd = rsqrtf(var + EPSf);
#pragma unroll
    for (int j = 0; j < 4; j++) {
        int d = tid + (j << 8);
        out[(size_t)row * Dm + d] = (y[j] - mean) * rstd * g[d] + bb[d];
    }
}

// ---------------- quantum FFN + residual + LN (block per token) ----------------
__global__ __launch_bounds__(256) void quantum_tail(const float* __restrict__ x1,
                                                    const float* __restrict__ Win,
                                                    const float* __restrict__ b_in,
                                                    const float* __restrict__ Wout,
                                                    const float* __restrict__ b_out,
                                                    const float* __restrict__ ry,
                                                    const float* __restrict__ g2,
                                                    const float* __restrict__ b2,
                                                    float* __restrict__ out)
{
    const int row = blockIdx.x;
    const int tid = threadIdx.x;
    const int lane = tid & 31, wid = tid >> 5;
    const float* xr = x1 + (size_t)row * Dm;

    __shared__ float redw[64];
    __shared__ float angs[8];
    __shared__ float ezs[8];
    __shared__ float2 st[2][DIMq];

    float xv[4];
    float accq[8] = {0, 0, 0, 0, 0, 0, 0, 0};
#pragma unroll
    for (int j = 0; j < 4; j++) {
        int d = tid + (j << 8);
        float xval = xr[d];
        xv[j] = xval;
#pragma unroll
        for (int qq = 0; qq < 8; qq++)
            accq[qq] = fmaf(xval, Win[qq * Dm + d], accq[qq]);
    }
#pragma unroll
    for (int qq = 0; qq < 8; qq++) {
        float vsum = accq[qq];
#pragma unroll
        for (int off = 16; off; off >>= 1)
            vsum += __shfl_xor_sync(0xffffffffu, vsum, off);
        if (lane == 0) redw[wid * 8 + qq] = vsum;
    }
    __syncthreads();
    if (tid < 8) {
        float s = b_in[tid];
#pragma unroll
        for (int w = 0; w < 8; w++) s += redw[w * 8 + tid];
        angs[tid] = s * 0.5f;
    }
    st[0][tid] = make_float2(tid == 0 ? 1.f : 0.f, 0.f);
    __syncthreads();

    int curb = 0;
#pragma unroll
    for (int w = 0; w < 8; w++) {
        int mask = 1 << (7 - w);
        float sn, cs;
        __sincosf(angs[w], &sn, &cs);
        float2 a  = st[curb][tid];
        float2 bb = st[curb][tid ^ mask];
        st[curb ^ 1][tid] = make_float2(fmaf(cs, a.x,  sn * bb.y),
                                        fmaf(cs, a.y, -sn * bb.x));
        curb ^= 1;
        __syncthreads();
    }
#pragma unroll
    for (int w = 0; w < 8; w++) {
        int mask = 1 << (7 - w);
        float sn, cs;
        __sincosf(ry[w] * 0.5f, &sn, &cs);
        float2 a  = st[curb][tid];
        float2 bb = st[curb][tid ^ mask];
        float sg = (tid & mask) ? sn : -sn;
        st[curb ^ 1][tid] = make_float2(fmaf(cs, a.x, sg * bb.x),
                                        fmaf(cs, a.y, sg * bb.y));
        curb ^= 1;
        __syncthreads();
    }
    int src = tid;
#pragma unroll
    for (int c = 6; c >= 0; c--) {
        int cmask = 1 << (7 - c);
        int tmask = cmask >> 1;
        if (src & cmask) src ^= tmask;
    }
    float2 fa = st[curb][src];
    float p = fa.x * fa.x + fa.y * fa.y;

#pragma unroll
    for (int w = 0; w < 8; w++) {
        float vsum = ((tid >> (7 - w)) & 1) ? -p : p;
#pragma unroll
        for (int off = 16; off; off >>= 1)
            vsum += __shfl_xor_sync(0xffffffffu, vsum, off);
        if (lane == 0) redw[wid * 8 + w] = vsum;
    }
    __syncthreads();
    if (tid < 8) {
        float s = 0.f;
#pragma unroll
        for (int w = 0; w < 8; w++) s += redw[w * 8 + tid];
        ezs[tid] = s;
    }
    __syncthreads();
    float e[8];
#pragma unroll
    for (int qq = 0; qq < 8; qq++) e[qq] = ezs[qq];

    float y[4], sum = 0.f, sq = 0.f;
#pragma unroll
    for (int j = 0; j < 4; j++) {
        int d = tid + (j << 8);
        const float4* wrow = reinterpret_cast<const float4*>(Wout + (size_t)d * 8);
        float4 w0 = wrow[0], w1 = wrow[1];
        float acc = b_out[d];
        acc = fmaf(e[0], w0.x, acc); acc = fmaf(e[1], w0.y, acc);
        acc = fmaf(e[2], w0.z, acc); acc = fmaf(e[3], w0.w, acc);
        acc = fmaf(e[4], w1.x, acc); acc = fmaf(e[5], w1.y, acc);
        acc = fmaf(e[6], w1.z, acc); acc = fmaf(e[7], w1.w, acc);
        acc = fmaxf(acc, 0.f);
        float yv = xv[j] + acc;
        y[j] = yv; sum += yv; sq = fmaf(yv, yv, sq);
    }
    __syncthreads();
#pragma unroll
    for (int off = 16; off; off >>= 1) {
        sum += __shfl_xor_sync(0xffffffffu, sum, off);
        sq  += __shfl_xor_sync(0xffffffffu, sq, off);
    }
    if (lane == 0) { redw[wid] = sum; redw[8 + wid] = sq; }
    __syncthreads();
    float tsum = 0.f, tsq = 0.f;
#pragma unroll
    for (int w = 0; w < 8; w++) { tsum += redw[w]; tsq += redw[8 + w]; }
    float mean = tsum * (1.f / 1024.f);
    float var  = tsq * (1.f / 1024.f) - mean * mean;
    float rstd = rsqrtf(var + EPSf);
#pragma unroll
    for (int j = 0; j < 4; j++) {
        int d = tid + (j << 8);
        out[(size_t)row * Dm + d] = (y[j] - mean) * rstd * g2[d] + b2[d];
    }
}

// ---------------- launch ----------------
extern "C" void kernel_launch(void* const* d_in, const int* in_sizes, int n_in,
                              void* d_out, int out_size)
{
    const float* x     = (const float*)d_in[0];
    const float* Wq    = (const float*)d_in[1];
    const float* Wk    = (const float*)d_in[2];
    const float* Wv    = (const float*)d_in[3];
    const float* Wo    = (const float*)d_in[4];
    const float* g1    = (const float*)d_in[5];
    const float* b1    = (const float*)d_in[6];
    const float* g2    = (const float*)d_in[7];
    const float* b2    = (const float*)d_in[8];
    const float* Win   = (const float*)d_in[9];
    const float* b_in  = (const float*)d_in[10];
    const float* Wout  = (const float*)d_in[11];
    const float* b_out = (const float*)d_in[12];
    const float* ry    = (const float*)d_in[13];
    float* out = (float*)d_out;

    float *q, *k, *v, *o, *proj, *x1;
    cudaGetSymbolAddress((void**)&q,    g_q);
    cudaGetSymbolAddress((void**)&k,    g_k);
    cudaGetSymbolAddress((void**)&v,    g_v);
    cudaGetSymbolAddress((void**)&o,    g_o);
    cudaGetSymbolAddress((void**)&proj, g_proj);
    cudaGetSymbolAddress((void**)&x1,   g_x1);

    const int attn_smem = 4 * 64 * ATT_PAD * (int)sizeof(float);
    cudaFuncSetAttribute(flash_attn, cudaFuncAttributeMaxDynamicSharedMemorySize, attn_smem);
    cudaFuncSetAttribute(gemm_mma, cudaFuncAttributeMaxDynamicSharedMemorySize, GSMEM);

    dim3 ggrid(Dm / BN, Mtot / BM);   // (4, 32) = 128 CTAs
    gemm_mma<<<ggrid, 256, GSMEM>>>(x, Wq, q);
    gemm_mma<<<ggrid, 256, GSMEM>>>(x, Wk, k);
    gemm_mma<<<ggrid, 256, GSMEM>>>(x, Wv, v);
    flash_attn<<<dim3(Sq / 64, Hh, Bsz), 256, attn_smem>>>(q, k, v, o);
    gemm_mma<<<ggrid, 256, GSMEM>>>(o, Wo, proj);
    add_ln<<<Mtot, 256>>>(x, proj, g1, b1, x1);
    quantum_tail<<<Mtot, 256>>>(x1, Win, b_in, Wout, b_out, ry, g2, b2, out);
}

// round 4
// speedup vs baseline: 3.9221x; 2.7999x over previous
#include <cuda_runtime.h>
#include <math.h>
#include <cstdint>

#define Bsz   2
#define Sq    2048
#define Dm    1024
#define Hh    16
#define Mtot  4096
#define DIMq  256
#define EPSf  1e-5f

// ---------------- scratch (device globals; no allocs allowed) ----------------
__device__ float g_q[Mtot * Dm];
__device__ float g_k[Mtot * Dm];
__device__ float g_v[Mtot * Dm];
__device__ float g_o[Mtot * Dm];
__device__ float g_proj[Mtot * Dm];
__device__ float g_x1[Mtot * Dm];

// ======================= helpers =======================
__device__ __forceinline__ uint32_t smem_to_u32(const void* p) {
    uint32_t a;
    asm("{ .reg .u64 t; cvta.to.shared.u64 t, %1; cvt.u32.u64 %0, t; }" : "=r"(a) : "l"(p));
    return a;
}
__device__ __forceinline__ void cp16(uint32_t sm, const void* g) {
    asm volatile("cp.async.cg.shared.global [%0], [%1], 16;" :: "r"(sm), "l"(g));
}
__device__ __forceinline__ void cp_commit() {
    asm volatile("cp.async.commit_group;");
}
template <int N>
__device__ __forceinline__ void cp_wait() {
    asm volatile("cp.async.wait_group %0;" :: "n"(N));
}
__device__ __forceinline__ uint32_t f2tf32(float x) {
    uint32_t r;
    asm("cvt.rna.tf32.f32 %0, %1;" : "=r"(r) : "f"(x));
    return r;
}
__device__ __forceinline__ void mma_tf32(float c[4], const uint32_t a[4], const uint32_t b[2]) {
    asm volatile(
        "mma.sync.aligned.m16n8k8.row.col.f32.tf32.tf32.f32 "
        "{%0,%1,%2,%3}, {%4,%5,%6,%7}, {%8,%9}, {%0,%1,%2,%3};"
        : "+f"(c[0]), "+f"(c[1]), "+f"(c[2]), "+f"(c[3])
        : "r"(a[0]), "r"(a[1]), "r"(a[2]), "r"(a[3]), "r"(b[0]), "r"(b[1]));
}

// ============ tf32 mma.sync GEMM: C[M,1024] = A[M,1024] * W[1024,1024]^T =====
#define BM 128
#define BN 256
#define BK 32
#define LDP 36
#define A_STAGE_B (BM * LDP * 4)
#define B_STAGE_B (BN * LDP * 4)
#define GSMEM (3 * (A_STAGE_B + B_STAGE_B))
#define NKT (Dm / BK)

__global__ __launch_bounds__(256, 1) void gemm_mma(const float* __restrict__ A,
                                                   const float* __restrict__ W,
                                                   float* __restrict__ C)
{
    extern __shared__ __align__(16) char gsm[];
    const uint32_t usm = smem_to_u32(gsm);
    const uint32_t usmA = usm;
    const uint32_t usmB = usm + 3 * A_STAGE_B;

    const int tid  = threadIdx.x;
    const int wid  = tid >> 5;
    const int lane = tid & 31;
    const int grp  = lane >> 2;
    const int tig  = lane & 3;
    const int wm   = wid >> 2;
    const int wn   = wid & 3;

    const int aRow0 = blockIdx.y * BM;
    const int bRow0 = blockIdx.x * BN;

    int aSm[4], bSm[8];
    int aGm[4], bGm[8];
#pragma unroll
    for (int i = 0; i < 4; i++) {
        int e = tid + (i << 8);
        int r = e >> 3, c4 = (e & 7) << 2;
        aSm[i] = (r * LDP + c4) * 4;
        aGm[i] = r * Dm + c4;
    }
#pragma unroll
    for (int i = 0; i < 8; i++) {
        int e = tid + (i << 8);
        int r = e >> 3, c4 = (e & 7) << 2;
        bSm[i] = (r * LDP + c4) * 4;
        bGm[i] = r * Dm + c4;
    }
    const float* gA = A + (size_t)aRow0 * Dm;
    const float* gB = W + (size_t)bRow0 * Dm;

    float acc[4][8][4];
#pragma unroll
    for (int im = 0; im < 4; im++)
#pragma unroll
        for (int jn = 0; jn < 8; jn++)
#pragma unroll
            for (int t = 0; t < 4; t++) acc[im][jn][t] = 0.f;

#pragma unroll
    for (int p = 0; p < 2; p++) {
        uint32_t sa = usmA + p * A_STAGE_B;
        uint32_t sb = usmB + p * B_STAGE_B;
        const float* ka = gA + p * BK;
        const float* kb = gB + p * BK;
#pragma unroll
        for (int i = 0; i < 4; i++) cp16(sa + aSm[i], ka + aGm[i]);
#pragma unroll
        for (int i = 0; i < 8; i++) cp16(sb + bSm[i], kb + bGm[i]);
        cp_commit();
    }

    for (int kt = 0; kt < NKT; kt++) {
        cp_wait<1>();
        __syncthreads();

        if (kt + 2 < NKT) {
            int s = (kt + 2) % 3;
            uint32_t sa = usmA + s * A_STAGE_B;
            uint32_t sb = usmB + s * B_STAGE_B;
            const float* ka = gA + (kt + 2) * BK;
            const float* kb = gB + (kt + 2) * BK;
#pragma unroll
            for (int i = 0; i < 4; i++) cp16(sa + aSm[i], ka + aGm[i]);
#pragma unroll
            for (int i = 0; i < 8; i++) cp16(sb + bSm[i], kb + bGm[i]);
        }
        cp_commit();

        const float* As = (const float*)(gsm + (kt % 3) * A_STAGE_B);
        const float* Bs = (const float*)(gsm + 3 * A_STAGE_B + (kt % 3) * B_STAGE_B);

#pragma unroll
        for (int k8 = 0; k8 < 4; k8++) {
            const int kb = k8 * 8 + tig;
            uint32_t afr[4][4], bfr[8][2];
#pragma unroll
            for (int im = 0; im < 4; im++) {
                int row = wm * 64 + im * 16 + grp;
                afr[im][0] = f2tf32(As[row * LDP + kb]);
                afr[im][1] = f2tf32(As[(row + 8) * LDP + kb]);
                afr[im][2] = f2tf32(As[row * LDP + kb + 4]);
                afr[im][3] = f2tf32(As[(row + 8) * LDP + kb + 4]);
            }
#pragma unroll
            for (int jn = 0; jn < 8; jn++) {
                int brow = wn * 64 + jn * 8 + grp;
                bfr[jn][0] = f2tf32(Bs[brow * LDP + kb]);
                bfr[jn][1] = f2tf32(Bs[brow * LDP + kb + 4]);
            }
#pragma unroll
            for (int im = 0; im < 4; im++)
#pragma unroll
                for (int jn = 0; jn < 8; jn++)
                    mma_tf32(acc[im][jn], afr[im], bfr[jn]);
        }
        __syncthreads();
    }

    const int rowBase = aRow0 + wm * 64;
    const int colBase = bRow0 + wn * 64;
#pragma unroll
    for (int im = 0; im < 4; im++) {
        int r0 = rowBase + im * 16 + grp;
#pragma unroll
        for (int jn = 0; jn < 8; jn++) {
            int col = colBase + jn * 8 + 2 * tig;
            float2 v01 = make_float2(acc[im][jn][0], acc[im][jn][1]);
            float2 v23 = make_float2(acc[im][jn][2], acc[im][jn][3]);
            *reinterpret_cast<float2*>(C + (size_t)r0 * Dm + col) = v01;
            *reinterpret_cast<float2*>(C + (size_t)(r0 + 8) * Dm + col) = v23;
        }
    }
}

// ============ Flash attention with tf32 mma.sync ============
// CTA: 128 Q rows, 8 warps (16 rows each). KV tiles of 64. head dim 64.
// smem (floats): Ps 128x68 (Q staging + P), Ks 2x 64x68, Vs 2x 64x72.
#define FA_PP 68
#define FA_PK 68
#define FA_PV 72
#define PS_OFF 0
#define KS_OFF (128 * FA_PP)                 // 8704
#define KS_STRIDE (64 * FA_PK)               // 4352
#define VS_OFF (KS_OFF + 2 * KS_STRIDE)      // 17408
#define VS_STRIDE (64 * FA_PV)               // 4608
#define FA_SMEM ((VS_OFF + 2 * VS_STRIDE) * 4)  // 106496 B
#define NKV (Sq / 64)                        // 32

__global__ __launch_bounds__(256, 1) void flash_mma(const float* __restrict__ q,
                                                    const float* __restrict__ k,
                                                    const float* __restrict__ v,
                                                    float* __restrict__ o)
{
    extern __shared__ __align__(16) float fsm[];
    const uint32_t usm = smem_to_u32(fsm);

    const int tid  = threadIdx.x;
    const int wid  = tid >> 5;
    const int lane = tid & 31;
    const int grp  = lane >> 2;
    const int tig  = lane & 3;

    const int b  = blockIdx.z;
    const int h  = blockIdx.y;
    const int q0 = blockIdx.x << 7;

    // global base pointers; row stride in gmem = Hh*64 = 1024 floats
    const float* qg = q + (((size_t)(b * Sq + q0) * Hh + h) << 6);
    const float* kg = k + (((size_t)(b * Sq) * Hh + h) << 6);
    const float* vg = v + (((size_t)(b * Sq) * Hh + h) << 6);

    // ---- prologue: stage Q (128x64) into Ps; prefetch K0,V0 and K1,V1 ----
    {
        // Q: 2048 float4 / 256 thr = 8 each
#pragma unroll
        for (int i = 0; i < 8; i++) {
            int e = tid + (i << 8);
            int r = e >> 4, c4 = (e & 15) << 2;
            cp16(usm + (PS_OFF + r * FA_PP + c4) * 4, qg + (size_t)r * 1024 + c4);
        }
        // K0,V0
#pragma unroll
        for (int i = 0; i < 4; i++) {
            int e = tid + (i << 8);
            int r = e >> 4, c4 = (e & 15) << 2;
            cp16(usm + (KS_OFF + r * FA_PK + c4) * 4, kg + (size_t)r * 1024 + c4);
            cp16(usm + (VS_OFF + r * FA_PV + c4) * 4, vg + (size_t)r * 1024 + c4);
        }
        cp_commit();
        // K1,V1
#pragma unroll
        for (int i = 0; i < 4; i++) {
            int e = tid + (i << 8);
            int r = e >> 4, c4 = (e & 15) << 2;
            cp16(usm + (KS_OFF + KS_STRIDE + r * FA_PK + c4) * 4, kg + (size_t)(64 + r) * 1024 + c4);
            cp16(usm + (VS_OFF + VS_STRIDE + r * FA_PV + c4) * 4, vg + (size_t)(64 + r) * 1024 + c4);
        }
        cp_commit();
    }
    cp_wait<1>();
    __syncthreads();

    // ---- Q fragments (scaled by 1/8), kept in registers all iterations ----
    const int lr0 = wid * 16 + grp;          // local Q row (first of pair)
    uint32_t qf[8][4];
#pragma unroll
    for (int k8 = 0; k8 < 8; k8++) {
        int kc = k8 * 8 + tig;
        qf[k8][0] = f2tf32(fsm[PS_OFF + lr0 * FA_PP + kc] * 0.125f);
        qf[k8][1] = f2tf32(fsm[PS_OFF + (lr0 + 8) * FA_PP + kc] * 0.125f);
        qf[k8][2] = f2tf32(fsm[PS_OFF + lr0 * FA_PP + kc + 4] * 0.125f);
        qf[k8][3] = f2tf32(fsm[PS_OFF + (lr0 + 8) * FA_PP + kc + 4] * 0.125f);
    }
    __syncthreads();   // all warps done reading Q before Ps is reused for P

    float m0 = -1e30f, m1 = -1e30f, l0 = 0.f, l1 = 0.f;
    float oac[8][4];
#pragma unroll
    for (int jd = 0; jd < 8; jd++)
#pragma unroll
        for (int t = 0; t < 4; t++) oac[jd][t] = 0.f;

    for (int it = 0; it < NKV; it++) {
        const int buf = it & 1;
        const float* Kb = fsm + KS_OFF + buf * KS_STRIDE;
        const float* Vb = fsm + VS_OFF + buf * VS_STRIDE;

        // ---- S = Q K^T ----
        float sac[8][4];
#pragma unroll
        for (int jn = 0; jn < 8; jn++)
#pragma unroll
            for (int t = 0; t < 4; t++) sac[jn][t] = 0.f;
#pragma unroll
        for (int k8 = 0; k8 < 8; k8++) {
            int kc = k8 * 8 + tig;
            uint32_t bfr[8][2];
#pragma unroll
            for (int jn = 0; jn < 8; jn++) {
                int krow = jn * 8 + grp;
                bfr[jn][0] = f2tf32(Kb[krow * FA_PK + kc]);
                bfr[jn][1] = f2tf32(Kb[krow * FA_PK + kc + 4]);
            }
#pragma unroll
            for (int jn = 0; jn < 8; jn++)
                mma_tf32(sac[jn], qf[k8], bfr[jn]);
        }

        // ---- online softmax (rows live in quads: shfl_xor 1,2) ----
        float mx0 = -1e30f, mx1 = -1e30f;
#pragma unroll
        for (int jn = 0; jn < 8; jn++) {
            mx0 = fmaxf(mx0, fmaxf(sac[jn][0], sac[jn][1]));
            mx1 = fmaxf(mx1, fmaxf(sac[jn][2], sac[jn][3]));
        }
        mx0 = fmaxf(mx0, __shfl_xor_sync(0xffffffffu, mx0, 1));
        mx0 = fmaxf(mx0, __shfl_xor_sync(0xffffffffu, mx0, 2));
        mx1 = fmaxf(mx1, __shfl_xor_sync(0xffffffffu, mx1, 1));
        mx1 = fmaxf(mx1, __shfl_xor_sync(0xffffffffu, mx1, 2));
        float mn0 = fmaxf(m0, mx0), mn1 = fmaxf(m1, mx1);
        float al0 = __expf(m0 - mn0), al1 = __expf(m1 - mn1);

        float sum0 = 0.f, sum1 = 0.f;
#pragma unroll
        for (int jn = 0; jn < 8; jn++) {
            float p00 = __expf(sac[jn][0] - mn0);
            float p01 = __expf(sac[jn][1] - mn0);
            float p10 = __expf(sac[jn][2] - mn1);
            float p11 = __expf(sac[jn][3] - mn1);
            int c = jn * 8 + 2 * tig;
            *reinterpret_cast<float2*>(&fsm[PS_OFF + lr0 * FA_PP + c])       = make_float2(p00, p01);
            *reinterpret_cast<float2*>(&fsm[PS_OFF + (lr0 + 8) * FA_PP + c]) = make_float2(p10, p11);
            sum0 += p00 + p01;
            sum1 += p10 + p11;
        }
        sum0 += __shfl_xor_sync(0xffffffffu, sum0, 1);
        sum0 += __shfl_xor_sync(0xffffffffu, sum0, 2);
        sum1 += __shfl_xor_sync(0xffffffffu, sum1, 1);
        sum1 += __shfl_xor_sync(0xffffffffu, sum1, 2);
        l0 = l0 * al0 + sum0;  m0 = mn0;
        l1 = l1 * al1 + sum1;  m1 = mn1;
#pragma unroll
        for (int jd = 0; jd < 8; jd++) {
            oac[jd][0] *= al0; oac[jd][1] *= al0;
            oac[jd][2] *= al1; oac[jd][3] *= al1;
        }
        __syncwarp();   // P tile is warp-private; order stores before reads

        // ---- O += P V ----
#pragma unroll
        for (int k8 = 0; k8 < 8; k8++) {
            int kc = k8 * 8 + tig;
            uint32_t afr[4];
            afr[0] = f2tf32(fsm[PS_OFF + lr0 * FA_PP + kc]);
            afr[1] = f2tf32(fsm[PS_OFF + (lr0 + 8) * FA_PP + kc]);
            afr[2] = f2tf32(fsm[PS_OFF + lr0 * FA_PP + kc + 4]);
            afr[3] = f2tf32(fsm[PS_OFF + (lr0 + 8) * FA_PP + kc + 4]);
            uint32_t bfr[8][2];
#pragma unroll
            for (int jd = 0; jd < 8; jd++) {
                int dcol = jd * 8 + grp;
                bfr[jd][0] = f2tf32(Vb[(k8 * 8 + tig) * FA_PV + dcol]);
                bfr[jd][1] = f2tf32(Vb[(k8 * 8 + tig + 4) * FA_PV + dcol]);
            }
#pragma unroll
            for (int jd = 0; jd < 8; jd++)
                mma_tf32(oac[jd], afr, bfr[jd]);
        }

        // ---- prefetch it+2 into buffer `buf` (safe after syncthreads) ----
        __syncthreads();
        if (it < NKV - 1) {
            if (it + 2 < NKV) {
                int kv0 = (it + 2) << 6;
#pragma unroll
                for (int i = 0; i < 4; i++) {
                    int e = tid + (i << 8);
                    int r = e >> 4, c4 = (e & 15) << 2;
                    cp16(usm + (KS_OFF + buf * KS_STRIDE + r * FA_PK + c4) * 4,
                         kg + (size_t)(kv0 + r) * 1024 + c4);
                    cp16(usm + (VS_OFF + buf * VS_STRIDE + r * FA_PV + c4) * 4,
                         vg + (size_t)(kv0 + r) * 1024 + c4);
                }
            }
            cp_commit();
            cp_wait<1>();
            __syncthreads();
        }
    }

    // ---- epilogue ----
    const float inv0 = 1.f / l0, inv1 = 1.f / l1;
    float* og = o + (((size_t)(b * Sq + q0 + lr0) * Hh + h) << 6);
    float* og8 = og + (size_t)8 * 1024;
#pragma unroll
    for (int jd = 0; jd < 8; jd++) {
        int c = jd * 8 + 2 * tig;
        *reinterpret_cast<float2*>(og + c)  = make_float2(oac[jd][0] * inv0, oac[jd][1] * inv0);
        *reinterpret_cast<float2*>(og8 + c) = make_float2(oac[jd][2] * inv1, oac[jd][3] * inv1);
    }
}

// ---------------- residual + LayerNorm ----------------
__global__ __launch_bounds__(256) void add_ln(const float* __restrict__ xa,
                                              const float* __restrict__ xb,
                                              const float* __restrict__ g,
                                              const float* __restrict__ bb,
                                              float* __restrict__ out)
{
    __shared__ float red[16];
    const int row = blockIdx.x, tid = threadIdx.x;
    const int lane = tid & 31, wid = tid >> 5;
    const float* pa = xa + (size_t)row * Dm;
    const float* pb = xb + (size_t)row * Dm;

    float y[4], sum = 0.f, sq = 0.f;
#pragma unroll
    for (int j = 0; j < 4; j++) {
        int d = tid + (j << 8);
        float yv = pa[d] + pb[d];
        y[j] = yv; sum += yv; sq = fmaf(yv, yv, sq);
    }
#pragma unroll
    for (int off = 16; off; off >>= 1) {
        sum += __shfl_xor_sync(0xffffffffu, sum, off);
        sq  += __shfl_xor_sync(0xffffffffu, sq, off);
    }
    if (lane == 0) { red[wid] = sum; red[8 + wid] = sq; }
    __syncthreads();
    float tsum = 0.f, tsq = 0.f;
#pragma unroll
    for (int w = 0; w < 8; w++) { tsum += red[w]; tsq += red[8 + w]; }
    float mean = tsum * (1.f / 1024.f);
    float var  = tsq * (1.f / 1024.f) - mean * mean;
    float rstd = rsqrtf(var + EPSf);
#pragma unroll
    for (int j = 0; j < 4; j++) {
        int d = tid + (j << 8);
        out[(size_t)row * Dm + d] = (y[j] - mean) * rstd * g[d] + bb[d];
    }
}

// ---------------- quantum FFN + residual + LN (block per token) ----------------
__global__ __launch_bounds__(256) void quantum_tail(const float* __restrict__ x1,
                                                    const float* __restrict__ Win,
                                                    const float* __restrict__ b_in,
                                                    const float* __restrict__ Wout,
                                                    const float* __restrict__ b_out,
                                                    const float* __restrict__ ry,
                                                    const float* __restrict__ g2,
                                                    const float* __restrict__ b2,
                                                    float* __restrict__ out)
{
    const int row = blockIdx.x;
    const int tid = threadIdx.x;
    const int lane = tid & 31, wid = tid >> 5;
    const float* xr = x1 + (size_t)row * Dm;

    __shared__ float redw[64];
    __shared__ float angs[8];
    __shared__ float ezs[8];
    __shared__ float2 st[2][DIMq];

    float xv[4];
    float accq[8] = {0, 0, 0, 0, 0, 0, 0, 0};
#pragma unroll
    for (int j = 0; j < 4; j++) {
        int d = tid + (j << 8);
        float xval = xr[d];
        xv[j] = xval;
#pragma unroll
        for (int qq = 0; qq < 8; qq++)
            accq[qq] = fmaf(xval, Win[qq * Dm + d], accq[qq]);
    }
#pragma unroll
    for (int qq = 0; qq < 8; qq++) {
        float vsum = accq[qq];
#pragma unroll
        for (int off = 16; off; off >>= 1)
            vsum += __shfl_xor_sync(0xffffffffu, vsum, off);
        if (lane == 0) redw[wid * 8 + qq] = vsum;
    }
    __syncthreads();
    if (tid < 8) {
        float s = b_in[tid];
#pragma unroll
        for (int w = 0; w < 8; w++) s += redw[w * 8 + tid];
        angs[tid] = s * 0.5f;
    }
    st[0][tid] = make_float2(tid == 0 ? 1.f : 0.f, 0.f);
    __syncthreads();

    int curb = 0;
#pragma unroll
    for (int w = 0; w < 8; w++) {
        int mask = 1 << (7 - w);
        float sn, cs;
        __sincosf(angs[w], &sn, &cs);
        float2 a  = st[curb][tid];
        float2 bb = st[curb][tid ^ mask];
        st[curb ^ 1][tid] = make_float2(fmaf(cs, a.x,  sn * bb.y),
                                        fmaf(cs, a.y, -sn * bb.x));
        curb ^= 1;
        __syncthreads();
    }
#pragma unroll
    for (int w = 0; w < 8; w++) {
        int mask = 1 << (7 - w);
        float sn, cs;
        __sincosf(ry[w] * 0.5f, &sn, &cs);
        float2 a  = st[curb][tid];
        float2 bb = st[curb][tid ^ mask];
        float sg = (tid & mask) ? sn : -sn;
        st[curb ^ 1][tid] = make_float2(fmaf(cs, a.x, sg * bb.x),
                                        fmaf(cs, a.y, sg * bb.y));
        curb ^= 1;
        __syncthreads();
    }
    int src = tid;
#pragma unroll
    for (int c = 6; c >= 0; c--) {
        int cmask = 1 << (7 - c);
        int tmask = cmask >> 1;
        if (src & cmask) src ^= tmask;
    }
    float2 fa = st[curb][src];
    float p = fa.x * fa.x + fa.y * fa.y;

#pragma unroll
    for (int w = 0; w < 8; w++) {
        float vsum = ((tid >> (7 - w)) & 1) ? -p : p;
#pragma unroll
        for (int off = 16; off; off >>= 1)
            vsum += __shfl_xor_sync(0xffffffffu, vsum, off);
        if (lane == 0) redw[wid * 8 + w] = vsum;
    }
    __syncthreads();
    if (tid < 8) {
        float s = 0.f;
#pragma unroll
        for (int w = 0; w < 8; w++) s += redw[w * 8 + tid];
        ezs[tid] = s;
    }
    __syncthreads();
    float e[8];
#pragma unroll
    for (int qq = 0; qq < 8; qq++) e[qq] = ezs[qq];

    float y[4], sum = 0.f, sq = 0.f;
#pragma unroll
    for (int j = 0; j < 4; j++) {
        int d = tid + (j << 8);
        const float4* wrow = reinterpret_cast<const float4*>(Wout + (size_t)d * 8);
        float4 w0 = wrow[0], w1 = wrow[1];
        float acc = b_out[d];
        acc = fmaf(e[0], w0.x, acc); acc = fmaf(e[1], w0.y, acc);
        acc = fmaf(e[2], w0.z, acc); acc = fmaf(e[3], w0.w, acc);
        acc = fmaf(e[4], w1.x, acc); acc = fmaf(e[5], w1.y, acc);
        acc = fmaf(e[6], w1.z, acc); acc = fmaf(e[7], w1.w, acc);
        acc = fmaxf(acc, 0.f);
        float yv = xv[j] + acc;
        y[j] = yv; sum += yv; sq = fmaf(yv, yv, sq);
    }
    __syncthreads();
#pragma unroll
    for (int off = 16; off; off >>= 1) {
        sum += __shfl_xor_sync(0xffffffffu, sum, off);
        sq  += __shfl_xor_sync(0xffffffffu, sq, off);
    }
    if (lane == 0) { redw[wid] = sum; redw[8 + wid] = sq; }
    __syncthreads();
    float tsum = 0.f, tsq = 0.f;
#pragma unroll
    for (int w = 0; w < 8; w++) { tsum += redw[w]; tsq += redw[8 + w]; }
    float mean = tsum * (1.f / 1024.f);
    float var  = tsq * (1.f / 1024.f) - mean * mean;
    float rstd = rsqrtf(var + EPSf);
#pragma unroll
    for (int j = 0; j < 4; j++) {
        int d = tid + (j << 8);
        out[(size_t)row * Dm + d] = (y[j] - mean) * rstd * g2[d] + b2[d];
    }
}

// ---------------- launch ----------------
extern "C" void kernel_launch(void* const* d_in, const int* in_sizes, int n_in,
                              void* d_out, int out_size)
{
    const float* x     = (const float*)d_in[0];
    const float* Wq    = (const float*)d_in[1];
    const float* Wk    = (const float*)d_in[2];
    const float* Wv    = (const float*)d_in[3];
    const float* Wo    = (const float*)d_in[4];
    const float* g1    = (const float*)d_in[5];
    const float* b1    = (const float*)d_in[6];
    const float* g2    = (const float*)d_in[7];
    const float* b2    = (const float*)d_in[8];
    const float* Win   = (const float*)d_in[9];
    const float* b_in  = (const float*)d_in[10];
    const float* Wout  = (const float*)d_in[11];
    const float* b_out = (const float*)d_in[12];
    const float* ry    = (const float*)d_in[13];
    float* out = (float*)d_out;

    float *q, *k, *v, *o, *proj, *x1;
    cudaGetSymbolAddress((void**)&q,    g_q);
    cudaGetSymbolAddress((void**)&k,    g_k);
    cudaGetSymbolAddress((void**)&v,    g_v);
    cudaGetSymbolAddress((void**)&o,    g_o);
    cudaGetSymbolAddress((void**)&proj, g_proj);
    cudaGetSymbolAddress((void**)&x1,   g_x1);

    cudaFuncSetAttribute(gemm_mma, cudaFuncAttributeMaxDynamicSharedMemorySize, GSMEM);
    cudaFuncSetAttribute(flash_mma, cudaFuncAttributeMaxDynamicSharedMemorySize, FA_SMEM);

    dim3 ggrid(Dm / BN, Mtot / BM);
    gemm_mma<<<ggrid, 256, GSMEM>>>(x, Wq, q);
    gemm_mma<<<ggrid, 256, GSMEM>>>(x, Wk, k);
    gemm_mma<<<ggrid, 256, GSMEM>>>(x, Wv, v);
    flash_mma<<<dim3(Sq / 128, Hh, Bsz), 256, FA_SMEM>>>(q, k, v, o);
    gemm_mma<<<ggrid, 256, GSMEM>>>(o, Wo, proj);
    add_ln<<<Mtot, 256>>>(x, proj, g1, b1, x1);
    quantum_tail<<<Mtot, 256>>>(x1, Win, b_in, Wout, b_out, ry, g2, b2, out);
}